// round 1
// baseline (speedup 1.0000x reference)
#include <cuda_runtime.h>
#include <math.h>

#define Bsz 8192
#define Hdim 1024
#define G4 4096

#define BM 128
#define BNU 32            // hidden units per block (x4 gates = 128 z-columns)
#define BK 16
#define NTHREADS 256
#define KTILES (Hdim / BK)   // 64

// Scratch (device globals: allocation-free per harness rules)
__device__ float g_Wsum[3ull * Hdim * G4];              // Wx[l] + Wh[l], l=0..2
__device__ float g_ha[(size_t)Bsz * Hdim];
__device__ float g_hb[(size_t)Bsz * Hdim];
__device__ float g_ca[(size_t)Bsz * Hdim];
__device__ float g_cb[(size_t)Bsz * Hdim];

__device__ __forceinline__ float to_tf32(float x) {
    float r;
    asm("cvt.rna.tf32.f32 %0, %1;" : "=f"(r) : "f"(x));
    return r;
}
__device__ __forceinline__ float sigm(float z) {
    return 1.0f / (1.0f + __expf(-z));
}
__device__ __forceinline__ void mma8(float& d0, float& d1, float& d2, float& d3,
                                     unsigned a0, unsigned a1, unsigned a2, unsigned a3,
                                     unsigned b0, unsigned b1) {
    asm volatile(
        "mma.sync.aligned.m16n8k8.row.col.f32.tf32.tf32.f32 "
        "{%0,%1,%2,%3}, {%4,%5,%6,%7}, {%8,%9}, {%0,%1,%2,%3};\n"
        : "+f"(d0), "+f"(d1), "+f"(d2), "+f"(d3)
        : "r"(a0), "r"(a1), "r"(a2), "r"(a3), "r"(b0), "r"(b1));
}

// Wsum[l] = Wx[l] + Wh[l]  (3*H*4H elements, float4 strided)
__global__ void wsum_kernel(const float4* __restrict__ Wx, const float4* __restrict__ Wh) {
    size_t i = (size_t)blockIdx.x * blockDim.x + threadIdx.x;   // < 3*H*4H/4
    float4 a = Wx[i], b = Wh[i];
    float4 o;
    o.x = a.x + b.x; o.y = a.y + b.y; o.z = a.z + b.z; o.w = a.w + b.w;
    ((float4*)g_Wsum)[i] = o;
}

// Fused z = h_in @ W + bias (+ x*Wx0 for layer 0) -> gates -> c_out, h_out
__global__ __launch_bounds__(NTHREADS)
void lstm_layer_kernel(int layer,
                       const float* __restrict__ xvec,
                       const float* __restrict__ c0,
                       const float* __restrict__ h0,
                       const float* __restrict__ Wx0,
                       const float* __restrict__ Wh0,
                       const float* __restrict__ b0,
                       const float* __restrict__ bl,
                       float* __restrict__ dout)
{
    const float *h_in, *c_in, *W, *bias;
    float *c_out, *h_out;
    if (layer == 0) {
        h_in = h0; c_in = c0; W = Wh0; bias = b0;
        c_out = g_ca; h_out = g_ha;
    } else if (layer == 1) {
        h_in = g_ha; c_in = g_ca; W = g_Wsum; bias = bl;
        c_out = g_cb; h_out = g_hb;
    } else if (layer == 2) {
        h_in = g_hb; c_in = g_cb; W = g_Wsum + (size_t)Hdim * G4; bias = bl + G4;
        c_out = g_ca; h_out = g_ha;
    } else {
        h_in = g_ha; c_in = g_ca; W = g_Wsum + 2ull * Hdim * G4; bias = bl + 2 * G4;
        c_out = dout; h_out = dout + (size_t)Bsz * Hdim;
    }

    __shared__ float As[2][BM][BK + 4];        // [m][k], pad -> conflict-free a-frags
    __shared__ float Bs[2][BK][4 * BNU + 8];   // [k][gate*32+u], pad 8 -> conflict-free b-frags

    const int tid  = threadIdx.x;
    const int lane = tid & 31;
    const int warp = tid >> 5;
    const int wm   = warp >> 1;     // 0..3  (32 rows each)
    const int wn   = warp & 1;      // 0..1  (16 units each)
    const int gid  = lane >> 2;     // 0..7
    const int tig  = lane & 3;      // 0..3

    const int rowBase = blockIdx.y * BM;
    const int uBase   = blockIdx.x * BNU;

    float acc[4][2][2][4];
    #pragma unroll
    for (int g = 0; g < 4; g++)
        #pragma unroll
        for (int a = 0; a < 2; a++)
            #pragma unroll
            for (int b = 0; b < 2; b++)
                #pragma unroll
                for (int r = 0; r < 4; r++) acc[g][a][b][r] = 0.0f;

    float4 aR[2], bR[2];

    auto loadG = [&](int kt) {
        #pragma unroll
        for (int i = 0; i < 2; i++) {
            int idx = tid + i * 256;
            int r = idx >> 2, kq = idx & 3;               // A: 128 rows x 4 float4
            aR[i] = *(const float4*)(h_in + (size_t)(rowBase + r) * Hdim + kt * BK + kq * 4);
            int kr = idx >> 5, cq = idx & 31;             // B: 16 k-rows x 32 float4
            int jl = cq * 4;
            int gate = jl >> 5, u = jl & 31;
            bR[i] = *(const float4*)(W + (size_t)(kt * BK + kr) * G4 + gate * 1024 + uBase + u);
        }
    };
    auto storeS = [&](int buf) {
        #pragma unroll
        for (int i = 0; i < 2; i++) {
            int idx = tid + i * 256;
            int r = idx >> 2, kq = idx & 3;
            As[buf][r][kq * 4 + 0] = to_tf32(aR[i].x);
            As[buf][r][kq * 4 + 1] = to_tf32(aR[i].y);
            As[buf][r][kq * 4 + 2] = to_tf32(aR[i].z);
            As[buf][r][kq * 4 + 3] = to_tf32(aR[i].w);
            int kr = idx >> 5, cq = idx & 31;
            int jl = cq * 4;
            Bs[buf][kr][jl + 0] = to_tf32(bR[i].x);
            Bs[buf][kr][jl + 1] = to_tf32(bR[i].y);
            Bs[buf][kr][jl + 2] = to_tf32(bR[i].z);
            Bs[buf][kr][jl + 3] = to_tf32(bR[i].w);
        }
    };
    auto compute = [&](int buf) {
        #pragma unroll
        for (int ks = 0; ks < 2; ks++) {
            const int k0 = ks * 8;
            unsigned afr[2][4];
            #pragma unroll
            for (int mt = 0; mt < 2; mt++) {
                int r0 = wm * 32 + mt * 16 + gid;
                afr[mt][0] = __float_as_uint(As[buf][r0    ][k0 + tig]);
                afr[mt][1] = __float_as_uint(As[buf][r0 + 8][k0 + tig]);
                afr[mt][2] = __float_as_uint(As[buf][r0    ][k0 + tig + 4]);
                afr[mt][3] = __float_as_uint(As[buf][r0 + 8][k0 + tig + 4]);
            }
            unsigned bfr[4][2][2];
            #pragma unroll
            for (int gate = 0; gate < 4; gate++)
                #pragma unroll
                for (int nt = 0; nt < 2; nt++) {
                    int cb = gate * 32 + wn * 16 + nt * 8 + gid;
                    bfr[gate][nt][0] = __float_as_uint(Bs[buf][k0 + tig    ][cb]);
                    bfr[gate][nt][1] = __float_as_uint(Bs[buf][k0 + tig + 4][cb]);
                }
            #pragma unroll
            for (int gate = 0; gate < 4; gate++)
                #pragma unroll
                for (int mt = 0; mt < 2; mt++)
                    #pragma unroll
                    for (int nt = 0; nt < 2; nt++)
                        mma8(acc[gate][mt][nt][0], acc[gate][mt][nt][1],
                             acc[gate][mt][nt][2], acc[gate][mt][nt][3],
                             afr[mt][0], afr[mt][1], afr[mt][2], afr[mt][3],
                             bfr[gate][nt][0], bfr[gate][nt][1]);
        }
    };

    loadG(0);
    storeS(0);
    __syncthreads();
    for (int kt = 0; kt < KTILES; kt++) {
        int cur = kt & 1;
        if (kt + 1 < KTILES) loadG(kt + 1);
        compute(cur);
        if (kt + 1 < KTILES) { storeS(cur ^ 1); __syncthreads(); }
    }

    // Epilogue: gates + cell update, written directly (no z round-trip)
    #pragma unroll
    for (int mt = 0; mt < 2; mt++) {
        #pragma unroll
        for (int half = 0; half < 2; half++) {
            int row = rowBase + wm * 32 + mt * 16 + gid + half * 8;
            float xr = 0.0f;
            if (layer == 0) xr = xvec[row];
            #pragma unroll
            for (int nt = 0; nt < 2; nt++) {
                int u0 = uBase + wn * 16 + nt * 8 + 2 * tig;
                #pragma unroll
                for (int p = 0; p < 2; p++) {
                    int u = u0 + p;
                    int reg = half * 2 + p;
                    float zi = acc[0][mt][nt][reg] + bias[u];
                    float zf = acc[1][mt][nt][reg] + bias[1024 + u];
                    float zg = acc[2][mt][nt][reg] + bias[2048 + u];
                    float zo = acc[3][mt][nt][reg] + bias[3072 + u];
                    if (layer == 0) {
                        zi += xr * Wx0[u];
                        zf += xr * Wx0[1024 + u];
                        zg += xr * Wx0[2048 + u];
                        zo += xr * Wx0[3072 + u];
                    }
                    float ig = sigm(zi);
                    float fg = sigm(zf);
                    float gg = tanhf(zg);
                    float og = sigm(zo);
                    size_t off = (size_t)row * Hdim + u;
                    float cn = fg * c_in[off] + ig * gg;
                    c_out[off] = cn;
                    h_out[off] = og * tanhf(cn);
                }
            }
        }
    }
}

// x_pred[b] = dot(h[b,:], Wd) + bd   (one warp per row)
__global__ void head_kernel(const float* __restrict__ h,
                            const float* __restrict__ Wd,
                            const float* __restrict__ bd,
                            float* __restrict__ out)
{
    int warpg = (blockIdx.x * blockDim.x + threadIdx.x) >> 5;
    int lane  = threadIdx.x & 31;
    const float4* hp = (const float4*)(h + (size_t)warpg * Hdim);
    const float4* wp = (const float4*)Wd;
    float s = 0.0f;
    #pragma unroll
    for (int i = 0; i < 8; i++) {
        float4 a = hp[lane + i * 32];
        float4 w = wp[lane + i * 32];
        s += a.x * w.x + a.y * w.y + a.z * w.z + a.w * w.w;
    }
    #pragma unroll
    for (int o = 16; o; o >>= 1) s += __shfl_xor_sync(0xffffffffu, s, o);
    if (lane == 0) out[warpg] = s + bd[0];
}

extern "C" void kernel_launch(void* const* d_in, const int* in_sizes, int n_in,
                              void* d_out, int out_size)
{
    const float* x    = (const float*)d_in[0];   // [8192,1]
    const float* c0   = (const float*)d_in[1];   // [8192,1024]
    const float* h0   = (const float*)d_in[2];   // [8192,1024]
    const float* Wx0  = (const float*)d_in[3];   // [1,4096]
    const float* Wh0  = (const float*)d_in[4];   // [1024,4096]
    const float* b0   = (const float*)d_in[5];   // [4096]
    const float* Wx   = (const float*)d_in[6];   // [3,1024,4096]
    const float* Wh   = (const float*)d_in[7];   // [3,1024,4096]
    const float* bb   = (const float*)d_in[8];   // [3,4096]
    const float* Wd   = (const float*)d_in[9];   // [1024,1]
    const float* bd   = (const float*)d_in[10];  // [1]
    float* out = (float*)d_out;                  // [c | h | x_pred]

    // Wsum = Wx + Wh (layers 1..3 fold both GEMMs into one)
    wsum_kernel<<<(3 * Hdim * G4 / 4) / 256, 256>>>((const float4*)Wx, (const float4*)Wh);

    dim3 grid(Hdim / BNU, Bsz / BM);   // 32 x 64
    for (int l = 0; l < 4; l++)
        lstm_layer_kernel<<<grid, NTHREADS>>>(l, x, c0, h0, Wx0, Wh0, b0, bb, out);

    head_kernel<<<Bsz / 8, 256>>>(out + (size_t)Bsz * Hdim, Wd, bd,
                                  out + 2ull * Bsz * Hdim);
}

// round 2
// speedup vs baseline: 1.0001x; 1.0001x over previous
#include <cuda_runtime.h>
#include <math.h>

#define Bsz 8192
#define Hdim 1024
#define G4 4096

#define BM 128
#define BNU 32            // hidden units per block (x4 gates = 128 z-columns)
#define BK 16
#define NTHREADS 256
#define KTILES (Hdim / BK)   // 64

// Scratch (device globals: allocation-free per harness rules)
__device__ float g_Wsum[3ull * Hdim * G4];              // Wx[l] + Wh[l], l=0..2
__device__ float g_ha[(size_t)Bsz * Hdim];
__device__ float g_hb[(size_t)Bsz * Hdim];
__device__ float g_ca[(size_t)Bsz * Hdim];
__device__ float g_cb[(size_t)Bsz * Hdim];

__device__ __forceinline__ float to_tf32(float x) {
    float r;
    asm("cvt.rna.tf32.f32 %0, %1;" : "=f"(r) : "f"(x));
    return r;
}
__device__ __forceinline__ float sigm(float z) {
    return 1.0f / (1.0f + __expf(-z));
}
__device__ __forceinline__ void mma8(float& d0, float& d1, float& d2, float& d3,
                                     unsigned a0, unsigned a1, unsigned a2, unsigned a3,
                                     unsigned b0, unsigned b1) {
    asm volatile(
        "mma.sync.aligned.m16n8k8.row.col.f32.tf32.tf32.f32 "
        "{%0,%1,%2,%3}, {%4,%5,%6,%7}, {%8,%9}, {%0,%1,%2,%3};\n"
        : "+f"(d0), "+f"(d1), "+f"(d2), "+f"(d3)
        : "r"(a0), "r"(a1), "r"(a2), "r"(a3), "r"(b0), "r"(b1));
}

// Wsum[l] = Wx[l] + Wh[l]  (3*H*4H elements, float4 strided)
__global__ void wsum_kernel(const float4* __restrict__ Wx, const float4* __restrict__ Wh) {
    size_t i = (size_t)blockIdx.x * blockDim.x + threadIdx.x;   // < 3*H*4H/4
    float4 a = Wx[i], b = Wh[i];
    float4 o;
    o.x = a.x + b.x; o.y = a.y + b.y; o.z = a.z + b.z; o.w = a.w + b.w;
    ((float4*)g_Wsum)[i] = o;
}

// Fused z = h_in @ W + bias (+ x*Wx0 for layer 0) -> gates -> c_out, h_out
__global__ __launch_bounds__(NTHREADS)
void lstm_layer_kernel(int layer,
                       const float* __restrict__ xvec,
                       const float* __restrict__ c0,
                       const float* __restrict__ h0,
                       const float* __restrict__ Wx0,
                       const float* __restrict__ Wh0,
                       const float* __restrict__ b0,
                       const float* __restrict__ bl,
                       float* __restrict__ dout)
{
    const float *h_in, *c_in, *W, *bias;
    float *c_out, *h_out;
    if (layer == 0) {
        h_in = h0; c_in = c0; W = Wh0; bias = b0;
        c_out = g_ca; h_out = g_ha;
    } else if (layer == 1) {
        h_in = g_ha; c_in = g_ca; W = g_Wsum; bias = bl;
        c_out = g_cb; h_out = g_hb;
    } else if (layer == 2) {
        h_in = g_hb; c_in = g_cb; W = g_Wsum + (size_t)Hdim * G4; bias = bl + G4;
        c_out = g_ca; h_out = g_ha;
    } else {
        h_in = g_ha; c_in = g_ca; W = g_Wsum + 2ull * Hdim * G4; bias = bl + 2 * G4;
        c_out = dout; h_out = dout + (size_t)Bsz * Hdim;
    }

    __shared__ float As[2][BM][BK + 4];        // [m][k], pad -> conflict-free a-frags
    __shared__ float Bs[2][BK][4 * BNU + 8];   // [k][gate*32+u], pad 8 -> conflict-free b-frags

    const int tid  = threadIdx.x;
    const int lane = tid & 31;
    const int warp = tid >> 5;
    const int wm   = warp >> 1;     // 0..3  (32 rows each)
    const int wn   = warp & 1;      // 0..1  (16 units each)
    const int gid  = lane >> 2;     // 0..7
    const int tig  = lane & 3;      // 0..3

    const int rowBase = blockIdx.y * BM;
    const int uBase   = blockIdx.x * BNU;

    float acc[4][2][2][4];
    #pragma unroll
    for (int g = 0; g < 4; g++)
        #pragma unroll
        for (int a = 0; a < 2; a++)
            #pragma unroll
            for (int b = 0; b < 2; b++)
                #pragma unroll
                for (int r = 0; r < 4; r++) acc[g][a][b][r] = 0.0f;

    float4 aR[2], bR[2];

    auto loadG = [&](int kt) {
        #pragma unroll
        for (int i = 0; i < 2; i++) {
            int idx = tid + i * 256;
            int r = idx >> 2, kq = idx & 3;               // A: 128 rows x 4 float4
            aR[i] = *(const float4*)(h_in + (size_t)(rowBase + r) * Hdim + kt * BK + kq * 4);
            int kr = idx >> 5, cq = idx & 31;             // B: 16 k-rows x 32 float4
            int jl = cq * 4;
            int gate = jl >> 5, u = jl & 31;
            bR[i] = *(const float4*)(W + (size_t)(kt * BK + kr) * G4 + gate * 1024 + uBase + u);
        }
    };
    auto storeS = [&](int buf) {
        #pragma unroll
        for (int i = 0; i < 2; i++) {
            int idx = tid + i * 256;
            int r = idx >> 2, kq = idx & 3;
            As[buf][r][kq * 4 + 0] = to_tf32(aR[i].x);
            As[buf][r][kq * 4 + 1] = to_tf32(aR[i].y);
            As[buf][r][kq * 4 + 2] = to_tf32(aR[i].z);
            As[buf][r][kq * 4 + 3] = to_tf32(aR[i].w);
            int kr = idx >> 5, cq = idx & 31;
            int jl = cq * 4;
            Bs[buf][kr][jl + 0] = to_tf32(bR[i].x);
            Bs[buf][kr][jl + 1] = to_tf32(bR[i].y);
            Bs[buf][kr][jl + 2] = to_tf32(bR[i].z);
            Bs[buf][kr][jl + 3] = to_tf32(bR[i].w);
        }
    };
    auto compute = [&](int buf) {
        #pragma unroll
        for (int ks = 0; ks < 2; ks++) {
            const int k0 = ks * 8;
            unsigned afr[2][4];
            #pragma unroll
            for (int mt = 0; mt < 2; mt++) {
                int r0 = wm * 32 + mt * 16 + gid;
                afr[mt][0] = __float_as_uint(As[buf][r0    ][k0 + tig]);
                afr[mt][1] = __float_as_uint(As[buf][r0 + 8][k0 + tig]);
                afr[mt][2] = __float_as_uint(As[buf][r0    ][k0 + tig + 4]);
                afr[mt][3] = __float_as_uint(As[buf][r0 + 8][k0 + tig + 4]);
            }
            unsigned bfr[4][2][2];
            #pragma unroll
            for (int gate = 0; gate < 4; gate++)
                #pragma unroll
                for (int nt = 0; nt < 2; nt++) {
                    int cb = gate * 32 + wn * 16 + nt * 8 + gid;
                    bfr[gate][nt][0] = __float_as_uint(Bs[buf][k0 + tig    ][cb]);
                    bfr[gate][nt][1] = __float_as_uint(Bs[buf][k0 + tig + 4][cb]);
                }
            #pragma unroll
            for (int gate = 0; gate < 4; gate++)
                #pragma unroll
                for (int mt = 0; mt < 2; mt++)
                    #pragma unroll
                    for (int nt = 0; nt < 2; nt++)
                        mma8(acc[gate][mt][nt][0], acc[gate][mt][nt][1],
                             acc[gate][mt][nt][2], acc[gate][mt][nt][3],
                             afr[mt][0], afr[mt][1], afr[mt][2], afr[mt][3],
                             bfr[gate][nt][0], bfr[gate][nt][1]);
        }
    };

    loadG(0);
    storeS(0);
    __syncthreads();
    for (int kt = 0; kt < KTILES; kt++) {
        int cur = kt & 1;
        if (kt + 1 < KTILES) loadG(kt + 1);
        compute(cur);
        if (kt + 1 < KTILES) { storeS(cur ^ 1); __syncthreads(); }
    }

    // Epilogue: gates + cell update, written directly (no z round-trip)
    #pragma unroll
    for (int mt = 0; mt < 2; mt++) {
        #pragma unroll
        for (int half = 0; half < 2; half++) {
            int row = rowBase + wm * 32 + mt * 16 + gid + half * 8;
            float xr = 0.0f;
            if (layer == 0) xr = xvec[row];
            #pragma unroll
            for (int nt = 0; nt < 2; nt++) {
                int u0 = uBase + wn * 16 + nt * 8 + 2 * tig;
                #pragma unroll
                for (int p = 0; p < 2; p++) {
                    int u = u0 + p;
                    int reg = half * 2 + p;
                    float zi = acc[0][mt][nt][reg] + bias[u];
                    float zf = acc[1][mt][nt][reg] + bias[1024 + u];
                    float zg = acc[2][mt][nt][reg] + bias[2048 + u];
                    float zo = acc[3][mt][nt][reg] + bias[3072 + u];
                    if (layer == 0) {
                        zi += xr * Wx0[u];
                        zf += xr * Wx0[1024 + u];
                        zg += xr * Wx0[2048 + u];
                        zo += xr * Wx0[3072 + u];
                    }
                    float ig = sigm(zi);
                    float fg = sigm(zf);
                    float gg = tanhf(zg);
                    float og = sigm(zo);
                    size_t off = (size_t)row * Hdim + u;
                    float cn = fg * c_in[off] + ig * gg;
                    c_out[off] = cn;
                    h_out[off] = og * tanhf(cn);
                }
            }
        }
    }
}

// x_pred[b] = dot(h[b,:], Wd) + bd   (one warp per row)
__global__ void head_kernel(const float* __restrict__ h,
                            const float* __restrict__ Wd,
                            const float* __restrict__ bd,
                            float* __restrict__ out)
{
    int warpg = (blockIdx.x * blockDim.x + threadIdx.x) >> 5;
    int lane  = threadIdx.x & 31;
    const float4* hp = (const float4*)(h + (size_t)warpg * Hdim);
    const float4* wp = (const float4*)Wd;
    float s = 0.0f;
    #pragma unroll
    for (int i = 0; i < 8; i++) {
        float4 a = hp[lane + i * 32];
        float4 w = wp[lane + i * 32];
        s += a.x * w.x + a.y * w.y + a.z * w.z + a.w * w.w;
    }
    #pragma unroll
    for (int o = 16; o; o >>= 1) s += __shfl_xor_sync(0xffffffffu, s, o);
    if (lane == 0) out[warpg] = s + bd[0];
}

extern "C" void kernel_launch(void* const* d_in, const int* in_sizes, int n_in,
                              void* d_out, int out_size)
{
    const float* x    = (const float*)d_in[0];   // [8192,1]
    const float* c0   = (const float*)d_in[1];   // [8192,1024]
    const float* h0   = (const float*)d_in[2];   // [8192,1024]
    const float* Wx0  = (const float*)d_in[3];   // [1,4096]
    const float* Wh0  = (const float*)d_in[4];   // [1024,4096]
    const float* b0   = (const float*)d_in[5];   // [4096]
    const float* Wx   = (const float*)d_in[6];   // [3,1024,4096]
    const float* Wh   = (const float*)d_in[7];   // [3,1024,4096]
    const float* bb   = (const float*)d_in[8];   // [3,4096]
    const float* Wd   = (const float*)d_in[9];   // [1024,1]
    const float* bd   = (const float*)d_in[10];  // [1]
    float* out = (float*)d_out;                  // [c | h | x_pred]

    // Wsum = Wx + Wh (layers 1..3 fold both GEMMs into one)
    wsum_kernel<<<(3 * Hdim * G4 / 4) / 256, 256>>>((const float4*)Wx, (const float4*)Wh);

    dim3 grid(Hdim / BNU, Bsz / BM);   // 32 x 64
    for (int l = 0; l < 4; l++)
        lstm_layer_kernel<<<grid, NTHREADS>>>(l, x, c0, h0, Wx0, Wh0, b0, bb, out);

    head_kernel<<<Bsz / 8, 256>>>(out + (size_t)Bsz * Hdim, Wd, bd,
                                  out + 2ull * Bsz * Hdim);
}

// round 4
// speedup vs baseline: 2.3570x; 2.3569x over previous
#include <cuda_runtime.h>
#include <cuda_fp16.h>
#include <cstdint>
#include <math.h>

#define Bsz 8192
#define Hdim 1024
#define G4 4096
#define HG (1024 * 4096)

#define BM 128      // batch rows per CTA
#define BN 128      // permuted z-cols per CTA (= 32 units x 4 gates)
#define BK 64       // K per pipeline chunk
#define NCHUNK (Hdim / BK)   // 16
#define NSTAGE 3
#define NTH 256

#define STAGE_BYTES 32768    // A: 128x64 half = 16KB ; B: 64x128 half = 16KB
#define STB_OFF 16384
#define SMEM_TOTAL (NSTAGE * STAGE_BYTES)

// ---------------- device scratch (allocation-free) ----------------
__device__ __half g_W[4ull * HG];        // permuted fp16 weights (L0: Wh0; L1-3: Wx+Wh)
__device__ __half g_h0h[Bsz * Hdim];     // fp16 h0
__device__ __half g_hah[Bsz * Hdim];
__device__ __half g_hbh[Bsz * Hdim];
__device__ float  g_ca[Bsz * Hdim];
__device__ float  g_cb[Bsz * Hdim];
__device__ float  g_biasp[4 * G4];       // permuted biases per layer
__device__ float  g_wx0p[G4];            // permuted Wx0

// permuted column layout: n' = (u>>2)*16 + (gate>>1)*8 + (u&3)*2 + (gate&1)
__device__ __forceinline__ int np_to_col(int np) {
    int u = ((np >> 4) << 2) | ((np >> 1) & 3);
    int gate = (((np >> 3) & 1) << 1) | (np & 1);
    return gate * 1024 + u;
}

__device__ __forceinline__ uint32_t smem_u32(const void* p) {
    uint32_t a;
    asm("{ .reg .u64 t; cvta.to.shared.u64 t, %1; cvt.u32.u64 %0, t; }" : "=r"(a) : "l"(p));
    return a;
}
__device__ __forceinline__ float sigm(float z) { return 1.0f / (1.0f + __expf(-z)); }
__device__ __forceinline__ float tanha(float x) {
    float r; asm("tanh.approx.f32 %0, %1;" : "=f"(r) : "f"(x)); return r;
}

#define CP16(dst, src) \
    asm volatile("cp.async.cg.shared.global [%0], [%1], 16;" :: "r"(dst), "l"(src) : "memory")
#define CPCOMMIT() asm volatile("cp.async.commit_group;" ::: "memory")
#define CPWAIT(n)  asm volatile("cp.async.wait_group %0;" :: "n"(n) : "memory")

#define LDSM4(r0, r1, r2, r3, a)                                              \
    asm volatile("ldmatrix.sync.aligned.m8n8.x4.shared.b16 {%0,%1,%2,%3}, [%4];" \
                 : "=r"(r0), "=r"(r1), "=r"(r2), "=r"(r3) : "r"(a))
#define LDSM4T(r0, r1, r2, r3, a)                                             \
    asm volatile("ldmatrix.sync.aligned.m8n8.x4.trans.shared.b16 {%0,%1,%2,%3}, [%4];" \
                 : "=r"(r0), "=r"(r1), "=r"(r2), "=r"(r3) : "r"(a))

__device__ __forceinline__ void mma16816(float* d, const uint32_t* a,
                                         uint32_t b0, uint32_t b1) {
    asm volatile(
        "mma.sync.aligned.m16n8k16.row.col.f32.f16.f16.f32 "
        "{%0,%1,%2,%3}, {%4,%5,%6,%7}, {%8,%9}, {%0,%1,%2,%3};\n"
        : "+f"(d[0]), "+f"(d[1]), "+f"(d[2]), "+f"(d[3])
        : "r"(a[0]), "r"(a[1]), "r"(a[2]), "r"(a[3]), "r"(b0), "r"(b1));
}

// ---------------- prep kernels ----------------
// g_W[l][k][n'] = fp16( (l==0 ? Wh0 : Wx[l-1]+Wh[l-1])[k][col(n')] )
__global__ void wprep_kernel(const float* __restrict__ Wh0,
                             const float* __restrict__ Wx,
                             const float* __restrict__ Wh) {
    size_t idx = (size_t)blockIdx.x * blockDim.x + threadIdx.x;  // < 4*HG
    int np = (int)(idx & 4095);
    size_t kl = idx >> 12;            // l*1024 + k
    int l = (int)(kl >> 10);
    size_t row = kl & 1023;
    int col = np_to_col(np);
    float v;
    if (l == 0) {
        v = Wh0[row * 4096 + col];
    } else {
        size_t o = (size_t)(l - 1) * HG + row * 4096 + col;
        v = Wx[o] + Wh[o];
    }
    g_W[idx] = __float2half_rn(v);
}
__global__ void hprep_kernel(const float* __restrict__ h0) {
    size_t i = (size_t)blockIdx.x * blockDim.x + threadIdx.x;  // < Bsz*Hdim
    g_h0h[i] = __float2half_rn(h0[i]);
}
// permuted biases + Wx0
__global__ void bprep_kernel(const float* __restrict__ b0,
                             const float* __restrict__ bb,
                             const float* __restrict__ Wx0) {
    int idx = blockIdx.x * blockDim.x + threadIdx.x;   // < 5*4096
    int np = idx & 4095;
    int l = idx >> 12;
    int col = np_to_col(np);
    if (l < 4) {
        g_biasp[idx] = (l == 0) ? b0[col] : bb[(l - 1) * G4 + col];
    } else {
        g_wx0p[np] = Wx0[col];
    }
}

// ---------------- fused LSTM layer (fp16 mma.sync + ldmatrix + cp.async) ----------------
__global__ void __launch_bounds__(NTH, 2)
lstm_layer_kernel(int layer,
                  const float* __restrict__ xvec,
                  const float* __restrict__ c0ext,
                  float* __restrict__ dout)
{
    const __half *A, *W;
    const float *c_in;
    float *c_out;
    __half *h_out_h;
    float *h_out_f;
    if (layer == 0) {
        A = g_h0h; c_in = c0ext; W = g_W;
        c_out = g_ca; h_out_h = g_hah; h_out_f = nullptr;
    } else if (layer == 1) {
        A = g_hah; c_in = g_ca; W = g_W + (size_t)HG;
        c_out = g_cb; h_out_h = g_hbh; h_out_f = nullptr;
    } else if (layer == 2) {
        A = g_hbh; c_in = g_cb; W = g_W + 2ull * HG;
        c_out = g_ca; h_out_h = g_hah; h_out_f = nullptr;
    } else {
        A = g_hah; c_in = g_ca; W = g_W + 3ull * HG;
        c_out = dout; h_out_h = nullptr; h_out_f = dout + (size_t)Bsz * Hdim;
    }
    const bool is_l0 = (layer == 0);
    const float* biasp = g_biasp + layer * G4;

    extern __shared__ char smem[];
    const uint32_t sb = smem_u32(smem);
    const int tid  = threadIdx.x;
    const int lane = tid & 31;
    const int wid  = tid >> 5;
    const int wm   = wid >> 2;        // 0..1  (64 m rows each)
    const int wn   = wid & 3;         // 0..3  (32 n' cols each)
    const int rowBase = blockIdx.y * BM;
    const int nBase   = blockIdx.x * BN;

    const __half* Abase = A + (size_t)rowBase * Hdim;
    const __half* Wbase = W + nBase;

    // ---- cp.async chunk loader (all 256 threads) ----
    auto load_chunk = [&](int s, int c) {
        const uint32_t stA = sb + s * STAGE_BYTES;
        const uint32_t stB = stA + STB_OFF;
        #pragma unroll
        for (int q = 0; q < 8; q++) {
            int i = tid + q * 256;       // 0..2047
            uint32_t dst; const __half* src;
            if (i < 1024) {              // A: 128 rows x 8 units(16B)
                int r = i >> 3, k16 = i & 7;
                dst = stA + r * 128 + 16 * (k16 ^ (r & 7));
                src = Abase + (size_t)r * Hdim + c * BK + k16 * 8;
            } else {                     // B: 64 k-rows x 16 units
                int j = i - 1024;
                int k = j >> 4, n16 = j & 15;
                dst = stB + k * 256 + 16 * (n16 ^ (k & 7));
                src = Wbase + (size_t)(c * BK + k) * G4 + n16 * 8;
            }
            CP16(dst, src);
        }
        CPCOMMIT();
    };

    float acc[4][4][4];
    #pragma unroll
    for (int mt = 0; mt < 4; mt++)
        #pragma unroll
        for (int j = 0; j < 4; j++)
            #pragma unroll
            for (int r = 0; r < 4; r++) acc[mt][j][r] = 0.0f;

    // per-lane ldmatrix address components
    const int arow = wm * 64 + (lane & 15);              // per mt: +mt*16
    const int ahi  = lane >> 4;                          // 0/1 (k-half unit)
    const int bm   = lane >> 3;                          // matrix id 0..3
    const int br   = lane & 7;                           // row within 8
    const int bkoff = br + (bm & 1) * 8;                 // k row offset within 16
    const int bnunit = wn * 4 + (bm >> 1);               // n' 16B-unit (+jp*... below)

    // prologue
    load_chunk(0, 0);
    load_chunk(1, 1);

    for (int c = 0; c < NCHUNK; c++) {
        const int s = c % NSTAGE;
        if (c + 1 < NCHUNK) { CPWAIT(1); } else { CPWAIT(0); }
        __syncthreads();
        if (c + 2 < NCHUNK) load_chunk((c + 2) % NSTAGE, c + 2);

        const uint32_t stA = sb + s * STAGE_BYTES;
        const uint32_t stB = stA + STB_OFF;
        #pragma unroll
        for (int ks = 0; ks < 4; ks++) {
            uint32_t af[4][4];
            #pragma unroll
            for (int mt = 0; mt < 4; mt++) {
                int rr = arow + mt * 16;
                uint32_t addr = stA + rr * 128 + 16 * (((2 * ks + ahi)) ^ (rr & 7));
                LDSM4(af[mt][0], af[mt][1], af[mt][2], af[mt][3], addr);
            }
            uint32_t bf[4][2];
            #pragma unroll
            for (int jp = 0; jp < 2; jp++) {
                int krow = ks * 16 + bkoff;
                uint32_t addr = stB + krow * 256 +
                                16 * ((bnunit + jp * 2) ^ (krow & 7));
                uint32_t r0, r1, r2, r3;
                LDSM4T(r0, r1, r2, r3, addr);
                bf[jp * 2 + 0][0] = r0; bf[jp * 2 + 0][1] = r1;
                bf[jp * 2 + 1][0] = r2; bf[jp * 2 + 1][1] = r3;
            }
            #pragma unroll
            for (int mt = 0; mt < 4; mt++)
                #pragma unroll
                for (int j = 0; j < 4; j++)
                    mma16816(acc[mt][j], af[mt], bf[j][0], bf[j][1]);
        }
        __syncthreads();
    }

    // ---- epilogue: gates + cell update in-register ----
    const int a4 = lane & 3;
    #pragma unroll
    for (int mt = 0; mt < 4; mt++) {
        #pragma unroll
        for (int rh = 0; rh < 2; rh++) {
            const int row = rowBase + wm * 64 + mt * 16 + (lane >> 2) + rh * 8;
            const float xr = is_l0 ? xvec[row] : 0.0f;
            #pragma unroll
            for (int g16 = 0; g16 < 2; g16++) {
                const int nl = wn * 32 + g16 * 16 + a4 * 2;     // n' of gate0
                const int u  = blockIdx.x * 32 + wn * 8 + g16 * 4 + a4;
                float zi = acc[mt][g16 * 2 + 0][rh * 2 + 0] + biasp[nBase + nl];
                float zf = acc[mt][g16 * 2 + 0][rh * 2 + 1] + biasp[nBase + nl + 1];
                float zg = acc[mt][g16 * 2 + 1][rh * 2 + 0] + biasp[nBase + nl + 8];
                float zo = acc[mt][g16 * 2 + 1][rh * 2 + 1] + biasp[nBase + nl + 9];
                if (is_l0) {
                    zi += xr * g_wx0p[nBase + nl];
                    zf += xr * g_wx0p[nBase + nl + 1];
                    zg += xr * g_wx0p[nBase + nl + 8];
                    zo += xr * g_wx0p[nBase + nl + 9];
                }
                const float ig = sigm(zi);
                const float fg = sigm(zf);
                const float gg = tanha(zg);
                const float og = sigm(zo);
                const size_t off = (size_t)row * Hdim + u;
                const float cn = fg * c_in[off] + ig * gg;
                c_out[off] = cn;
                const float hv = og * tanha(cn);
                if (h_out_f) h_out_f[off] = hv;
                else         h_out_h[off] = __float2half_rn(hv);
            }
        }
    }
}

// ---------------- prediction head ----------------
__global__ void head_kernel(const float* __restrict__ h,
                            const float* __restrict__ Wd,
                            const float* __restrict__ bd,
                            float* __restrict__ out)
{
    int warpg = (blockIdx.x * blockDim.x + threadIdx.x) >> 5;
    int lane = threadIdx.x & 31;
    const float4* hp = (const float4*)(h + (size_t)warpg * Hdim);
    const float4* wp = (const float4*)Wd;
    float s = 0.0f;
    #pragma unroll
    for (int i = 0; i < 8; i++) {
        float4 a = hp[lane + i * 32];
        float4 w = wp[lane + i * 32];
        s += a.x * w.x + a.y * w.y + a.z * w.z + a.w * w.w;
    }
    #pragma unroll
    for (int o = 16; o; o >>= 1) s += __shfl_xor_sync(0xffffffffu, s, o);
    if (lane == 0) out[warpg] = s + bd[0];
}

extern "C" void kernel_launch(void* const* d_in, const int* in_sizes, int n_in,
                              void* d_out, int out_size)
{
    const float* x   = (const float*)d_in[0];
    const float* c0  = (const float*)d_in[1];
    const float* h0  = (const float*)d_in[2];
    const float* Wx0 = (const float*)d_in[3];
    const float* Wh0 = (const float*)d_in[4];
    const float* b0  = (const float*)d_in[5];
    const float* Wx  = (const float*)d_in[6];
    const float* Wh  = (const float*)d_in[7];
    const float* bb  = (const float*)d_in[8];
    const float* Wd  = (const float*)d_in[9];
    const float* bd  = (const float*)d_in[10];
    float* out = (float*)d_out;  // [c | h | x_pred]

    cudaFuncSetAttribute(lstm_layer_kernel,
                         cudaFuncAttributeMaxDynamicSharedMemorySize, SMEM_TOTAL);

    wprep_kernel<<<(4ull * HG) / 256, 256>>>(Wh0, Wx, Wh);
    hprep_kernel<<<(Bsz * Hdim) / 256, 256>>>(h0);
    bprep_kernel<<<(5 * G4) / 256, 256>>>(b0, bb, Wx0);

    dim3 grid(G4 / BN, Bsz / BM);   // 32 x 64 = 2048 CTAs
    for (int l = 0; l < 4; l++)
        lstm_layer_kernel<<<grid, NTH, SMEM_TOTAL>>>(l, x, c0, out);

    head_kernel<<<Bsz / 8, 256>>>(out + (size_t)Bsz * Hdim, Wd, bd,
                                  out + 2ull * (size_t)Bsz * Hdim);
}